// round 1
// baseline (speedup 1.0000x reference)
#include <cuda_runtime.h>
#include <math.h>

// FLC pooling = frequency-domain low-pass crop + 2x downsample.
// Reduced to real GEMMs vs one circulant 112x112 matrix R (see derivation):
//   out = 0.25*x_ee + (0.5*x_eo + R*x_oo)*R^T + 0.5*R*x_oe - (s/224^2)*(-1)^(n1+n2)
// where R[n][j] = cor((n-j) mod 112), s = sum (-1)^(j1+j2) x_oo.

#define NIMG   1024      // 16*64
#define H      224
#define NH     112
#define TS_LD  225       // padded leading dim for Ts (avoid bank conflicts)
#define AB_LD  113       // padded leading dim for 112-wide buffers

__device__ float g_cor2[2 * NH];   // doubled circulant table: cor2[i] = cor(i mod 112)

// ---------------------------------------------------------------------------
// Init: build the circulant kernel table in fp64.
//   cor(t) = (1/224) * sum_{k=-56}^{55} cos(k * theta),  theta = pi*(2t-1)/112
// (imaginary part of the odd-tap kernel is exactly (1/224)(-1)^t and is
// handled analytically as a rank-1 correction; cos(56*theta) term is 0.)
// ---------------------------------------------------------------------------
__global__ void flc_cor_init_kernel() {
    int t = threadIdx.x;
    if (t < 2 * NH) {
        int tt = t % NH;
        double theta = 3.14159265358979323846 * (2.0 * tt - 1.0) / 112.0;
        double ssum = 0.0;
        for (int k = -56; k <= 55; ++k) ssum += cos((double)k * theta);
        g_cor2[t] = (float)(ssum / 224.0);
    }
}

// ---------------------------------------------------------------------------
// Fused per-image kernel. One block per image, 256 threads (16x16),
// thread tile 7x7 for both GEMMs. Dynamic smem ~203 KB.
// ---------------------------------------------------------------------------
__global__ __launch_bounds__(256, 1)
void flc_main_kernel(const float* __restrict__ x, float* __restrict__ out) {
    const int img = blockIdx.x;
    const float* __restrict__ xi = x + (size_t)img * H * H;
    float* __restrict__ oi = out + (size_t)img * NH * NH;

    extern __shared__ float sm[];
    float* Ts   = sm;                       // [112][225]  T = R * A (A = odd rows)
    float* Ab   = Ts + NH * TS_LD;          // [112][113]  A chunk, later reused as G2
    float* Epre = Ab + NH * AB_LD;          // [112][113]  0.25*x_ee + 0.5*T_even
    float* cor2 = Epre + NH * AB_LD;        // [224]
    float* sred = cor2 + 2 * NH;            // [8]

    const int tid = threadIdx.x;
    const int tx = tid & 15;
    const int ty = tid >> 4;

    if (tid < 2 * NH) cor2[tid] = g_cor2[tid];

    float s_local = 0.f;

    // ---------------- GEMM1: T[n][w] = sum_j cor2[n-j+112] * x[2j+1][w] -----
    for (int w0 = 0; w0 < H; w0 += NH) {
        // load A chunk (odd rows, columns w0..w0+111); fold in sign-sum s
        for (int idx = tid; idx < NH * NH; idx += 256) {
            int j = idx / NH;
            int w = idx - j * NH;
            float v = xi[(2 * j + 1) * H + w0 + w];
            Ab[j * AB_LD + w] = v;
            int gw = w0 + w;
            if (gw & 1) {                        // odd global column -> x_oo
                int j2 = gw >> 1;
                s_local += ((j + j2) & 1) ? -v : v;
            }
        }
        __syncthreads();

        float acc[7][7];
        #pragma unroll
        for (int i = 0; i < 7; ++i)
            #pragma unroll
            for (int c = 0; c < 7; ++c) acc[i][c] = 0.f;

        for (int j = 0; j < NH; ++j) {
            float rv[7], av[7];
            #pragma unroll
            for (int i = 0; i < 7; ++i) rv[i] = cor2[ty + 16 * i - j + NH];
            #pragma unroll
            for (int c = 0; c < 7; ++c) av[c] = Ab[j * AB_LD + tx + 16 * c];
            #pragma unroll
            for (int i = 0; i < 7; ++i)
                #pragma unroll
                for (int c = 0; c < 7; ++c)
                    acc[i][c] = fmaf(rv[i], av[c], acc[i][c]);
        }

        #pragma unroll
        for (int i = 0; i < 7; ++i)
            #pragma unroll
            for (int c = 0; c < 7; ++c)
                Ts[(ty + 16 * i) * TS_LD + w0 + tx + 16 * c] = acc[i][c];
        __syncthreads();
    }

    // ---------------- s reduction (deterministic tree) ----------------------
    #pragma unroll
    for (int o = 16; o; o >>= 1) s_local += __shfl_xor_sync(0xffffffffu, s_local, o);
    if ((tid & 31) == 0) sred[tid >> 5] = s_local;

    // ---------------- build G2 (reuse Ab) and Epre ---------------------------
    // G2[n1][j2]   = 0.5*x[2n1][2j2+1] + T[n1][2j2+1]
    // Epre[n1][n2] = 0.25*x[2n1][2n2]  + 0.5*T[n1][2n2]
    __syncthreads();   // guard Ab reuse & sred visibility
    for (int idx = tid; idx < NH * NH; idx += 256) {
        int n1 = idx / NH;
        int j2 = idx - n1 * NH;
        float2 px = *(const float2*)(xi + (2 * n1) * H + 2 * j2);
        Ab[n1 * AB_LD + j2]   = 0.5f  * px.y + Ts[n1 * TS_LD + 2 * j2 + 1];
        Epre[n1 * AB_LD + j2] = 0.25f * px.x + 0.5f * Ts[n1 * TS_LD + 2 * j2];
    }
    __syncthreads();

    float stot = 0.f;
    #pragma unroll
    for (int wi = 0; wi < 8; ++wi) stot += sred[wi];
    const float scorr = stot * (1.0f / 50176.0f);   // s / 224^2

    // ---------------- GEMM2: out = G2 * R^T + epilogue ----------------------
    float acc[7][7];
    #pragma unroll
    for (int i = 0; i < 7; ++i)
        #pragma unroll
        for (int c = 0; c < 7; ++c) acc[i][c] = 0.f;

    for (int j2 = 0; j2 < NH; ++j2) {
        float gv[7], rv[7];
        #pragma unroll
        for (int i = 0; i < 7; ++i) gv[i] = Ab[(ty + 16 * i) * AB_LD + j2];
        #pragma unroll
        for (int c = 0; c < 7; ++c) rv[c] = cor2[tx + 16 * c - j2 + NH];
        #pragma unroll
        for (int i = 0; i < 7; ++i)
            #pragma unroll
            for (int c = 0; c < 7; ++c)
                acc[i][c] = fmaf(gv[i], rv[c], acc[i][c]);
    }

    #pragma unroll
    for (int i = 0; i < 7; ++i) {
        int n1 = ty + 16 * i;
        #pragma unroll
        for (int c = 0; c < 7; ++c) {
            int n2 = tx + 16 * c;
            float r = acc[i][c] + Epre[n1 * AB_LD + n2];
            // - (-1)^(n1+n2) * scorr
            r += ((n1 + n2) & 1) ? scorr : -scorr;
            oi[n1 * NH + n2] = r;
        }
    }
}

extern "C" void kernel_launch(void* const* d_in, const int* in_sizes, int n_in,
                              void* d_out, int out_size) {
    (void)in_sizes; (void)n_in; (void)out_size;
    const float* x = (const float*)d_in[0];
    float* out = (float*)d_out;

    const int smem_bytes = (NH * TS_LD + 2 * NH * AB_LD + 2 * NH + 8) * (int)sizeof(float);
    cudaFuncSetAttribute(flc_main_kernel,
                         cudaFuncAttributeMaxDynamicSharedMemorySize, smem_bytes);

    flc_cor_init_kernel<<<1, 2 * NH>>>();
    flc_main_kernel<<<NIMG, 256, smem_bytes>>>(x, out);
}

// round 3
// speedup vs baseline: 2.2506x; 2.2506x over previous
#include <cuda_runtime.h>
#include <math.h>

// FLC pooling = fft2(forward) -> fftshift -> center crop (112x112) -> ifft2 -> real.
// Reduced to real GEMMs vs one circulant 112x112 matrix R:
//   out = 0.25*x_ee + (0.5*x_eo + R*x_oo)*R^T + 0.5*R*x_oe - (s/224^2)*(-1)^(n1+n2)
// where R[n][j] = cor((n-j) mod 112), s = sum (-1)^(j1+j2) x_oo, and the
// Dirichlet sum has closed form  cor(t) = -(-1)^t * cot(pi*(2t-1)/224) / 224.

#define NIMG   1024      // 16*64
#define H      224
#define NH     112
#define LD     113       // padded leading dim (bank-conflict avoidance)

__global__ __launch_bounds__(256, 2)
void flc_main_kernel(const float* __restrict__ x, float* __restrict__ out) {
    extern __shared__ float sm[];
    float* BufA = sm;               // [112][113]  x_oo, overwritten by G2
    float* BufB = BufA + NH * LD;   // [112][113]  x_oe, overwritten by Epre
    float* cor2 = BufB + NH * LD;   // [224] doubled circulant table
    float* sred = cor2 + 2 * NH;    // [8]

    const int tid = threadIdx.x;
    const int tx = tid & 15;
    const int ty = tid >> 4;
    const int img = blockIdx.x;
    const float* __restrict__ xi = x + (size_t)img * H * H;
    float* __restrict__ oi = out + (size_t)img * NH * NH;

    // Closed-form circulant table (doubled for mod-free indexing):
    //   cor2[i] = cor(i mod 112),  cor(t) = -(-1)^t * cot(pi(2t-1)/224)/224
    if (tid < 2 * NH) {
        int t = tid % NH;
        double th = 3.14159265358979323846 * (2.0 * (double)t - 1.0) / 224.0;
        double c = cos(th) / sin(th) * (1.0 / 224.0);
        cor2[tid] = (float)((t & 1) ? c : -c);
    }

    // ---- load odd rows as float2 pairs: .x = x_oe, .y = x_oo; fold sign-sum s
    float s_local = 0.f;
    for (int idx = tid; idx < NH * NH; idx += 256) {
        int j = idx / NH;
        int w = idx - j * NH;
        float2 p = *(const float2*)(xi + (2 * j + 1) * H + 2 * w);
        BufB[j * LD + w] = p.x;
        BufA[j * LD + w] = p.y;
        s_local += ((j + w) & 1) ? -p.y : p.y;
    }
    // deterministic s reduction
    #pragma unroll
    for (int o = 16; o; o >>= 1) s_local += __shfl_xor_sync(0xffffffffu, s_local, o);
    if ((tid & 31) == 0) sred[tid >> 5] = s_local;
    __syncthreads();

    const int row0 = ty;            // rows handled: ty + 16*i
    const int col0 = tx;            // cols handled: tx + 16*c

    // ---- GEMM1a: T_oo = R * x_oo; overwrite BufA with G2 = T_oo + 0.5*x_eo
    {
        float acc[7][7];
        #pragma unroll
        for (int i = 0; i < 7; ++i)
            #pragma unroll
            for (int c = 0; c < 7; ++c) acc[i][c] = 0.f;

        for (int j = 0; j < NH; ++j) {
            float rv[7], av[7];
            #pragma unroll
            for (int i = 0; i < 7; ++i) rv[i] = cor2[row0 + 16 * i - j + NH];
            #pragma unroll
            for (int c = 0; c < 7; ++c) av[c] = BufA[j * LD + col0 + 16 * c];
            #pragma unroll
            for (int i = 0; i < 7; ++i)
                #pragma unroll
                for (int c = 0; c < 7; ++c)
                    acc[i][c] = fmaf(rv[i], av[c], acc[i][c]);
        }
        __syncthreads();
        #pragma unroll
        for (int i = 0; i < 7; ++i) {
            int n1 = row0 + 16 * i;
            #pragma unroll
            for (int c = 0; c < 7; ++c) {
                int j2 = col0 + 16 * c;
                BufA[n1 * LD + j2] = acc[i][c] + 0.5f * xi[(2 * n1) * H + 2 * j2 + 1];
            }
        }
        __syncthreads();
    }

    // ---- GEMM1b: T_oe = R * x_oe; overwrite BufB with Epre = 0.5*T_oe + 0.25*x_ee
    {
        float acc[7][7];
        #pragma unroll
        for (int i = 0; i < 7; ++i)
            #pragma unroll
            for (int c = 0; c < 7; ++c) acc[i][c] = 0.f;

        for (int j = 0; j < NH; ++j) {
            float rv[7], bv[7];
            #pragma unroll
            for (int i = 0; i < 7; ++i) rv[i] = cor2[row0 + 16 * i - j + NH];
            #pragma unroll
            for (int c = 0; c < 7; ++c) bv[c] = BufB[j * LD + col0 + 16 * c];
            #pragma unroll
            for (int i = 0; i < 7; ++i)
                #pragma unroll
                for (int c = 0; c < 7; ++c)
                    acc[i][c] = fmaf(rv[i], bv[c], acc[i][c]);
        }
        __syncthreads();
        #pragma unroll
        for (int i = 0; i < 7; ++i) {
            int n1 = row0 + 16 * i;
            #pragma unroll
            for (int c = 0; c < 7; ++c) {
                int n2 = col0 + 16 * c;
                BufB[n1 * LD + n2] = 0.5f * acc[i][c] + 0.25f * xi[(2 * n1) * H + 2 * n2];
            }
        }
        __syncthreads();
    }

    float stot = 0.f;
    #pragma unroll
    for (int wi = 0; wi < 8; ++wi) stot += sred[wi];
    const float scorr = stot * (1.0f / 50176.0f);   // s / 224^2

    // ---- GEMM2: out = G2 * R^T + Epre -/+ scorr
    {
        float acc[7][7];
        #pragma unroll
        for (int i = 0; i < 7; ++i)
            #pragma unroll
            for (int c = 0; c < 7; ++c) acc[i][c] = 0.f;

        for (int j2 = 0; j2 < NH; ++j2) {
            float gv[7], rv[7];
            #pragma unroll
            for (int i = 0; i < 7; ++i) gv[i] = BufA[(row0 + 16 * i) * LD + j2];
            #pragma unroll
            for (int c = 0; c < 7; ++c) rv[c] = cor2[col0 + 16 * c - j2 + NH];
            #pragma unroll
            for (int i = 0; i < 7; ++i)
                #pragma unroll
                for (int c = 0; c < 7; ++c)
                    acc[i][c] = fmaf(gv[i], rv[c], acc[i][c]);
        }

        #pragma unroll
        for (int i = 0; i < 7; ++i) {
            int n1 = row0 + 16 * i;
            #pragma unroll
            for (int c = 0; c < 7; ++c) {
                int n2 = col0 + 16 * c;
                float r = acc[i][c] + BufB[n1 * LD + n2];
                r += ((n1 + n2) & 1) ? scorr : -scorr;
                oi[n1 * NH + n2] = r;
            }
        }
    }
}

extern "C" void kernel_launch(void* const* d_in, const int* in_sizes, int n_in,
                              void* d_out, int out_size) {
    (void)in_sizes; (void)n_in; (void)out_size;
    const float* x = (const float*)d_in[0];
    float* out = (float*)d_out;

    const int smem_bytes = (2 * NH * LD + 2 * NH + 8) * (int)sizeof(float);
    cudaFuncSetAttribute(flc_main_kernel,
                         cudaFuncAttributeMaxDynamicSharedMemorySize, smem_bytes);

    flc_main_kernel<<<NIMG, 256, smem_bytes>>>(x, out);
}

// round 6
// speedup vs baseline: 2.3566x; 1.0471x over previous
#include <cuda_runtime.h>
#include <math.h>

// FLC pooling = fft2(forward) -> fftshift -> center crop (112x112) -> ifft2 -> real.
// Reduced to real GEMMs vs one circulant 112x112 matrix R:
//   out = 0.25*x_ee + (0.5*x_eo + R*x_oo)*R^T + 0.5*R*x_oe - (s/224^2)*(-1)^(n1+n2)
// where R[n][j] = cor((n-j) mod 112), s = sum (-1)^(j1+j2) x_oo, and the
// Dirichlet sum has closed form  cor(t) = -(-1)^t * cot(pi*(2t-1)/224) / 224.
// Inner loops use packed fma.rn.f32x2 (FFMA2): 2 MACs per fma-pipe issue.

#define NIMG   1024      // 16*64
#define H      224
#define NH     112
#define LD     113       // padded leading dim (bank-conflict avoidance)

typedef unsigned long long u64;

__device__ __forceinline__ u64 pack2(float lo, float hi) {
    u64 r;
    asm("mov.b64 %0, {%1, %2};" : "=l"(r) : "f"(lo), "f"(hi));
    return r;
}
__device__ __forceinline__ void fma2(u64& d, u64 a, u64 b) {
    asm("fma.rn.f32x2 %0, %1, %2, %0;" : "+l"(d) : "l"(a), "l"(b));
}
__device__ __forceinline__ float2 unpack2(u64 v) {
    float lo, hi;
    asm("mov.b64 {%0, %1}, %2;" : "=f"(lo), "=f"(hi) : "l"(v));
    return make_float2(lo, hi);
}

__global__ __launch_bounds__(256, 2)
void flc_main_kernel(const float* __restrict__ x, float* __restrict__ out) {
    extern __shared__ float sm[];
    float* BufA = sm;               // [112][113]  x_oo, overwritten by G2
    float* BufB = BufA + NH * LD;   // [112][113]  x_oe, overwritten by Epre
    float* cor2 = BufB + NH * LD;   // [224] doubled circulant table
    float* sred = cor2 + 2 * NH;    // [8]

    const int tid = threadIdx.x;
    const int tx = tid & 15;
    const int ty = tid >> 4;
    const int img = blockIdx.x;
    const float* __restrict__ xi = x + (size_t)img * H * H;
    float* __restrict__ oi = out + (size_t)img * NH * NH;

    // Closed-form circulant table (doubled for mod-free indexing)
    if (tid < 2 * NH) {
        int t = tid % NH;
        double th = 3.14159265358979323846 * (2.0 * (double)t - 1.0) / 224.0;
        double c = cos(th) / sin(th) * (1.0 / 224.0);
        cor2[tid] = (float)((t & 1) ? c : -c);
    }

    // ---- load odd rows as float2 pairs: .x = x_oe, .y = x_oo; fold sign-sum s
    float s_local = 0.f;
    for (int idx = tid; idx < NH * NH; idx += 256) {
        int j = idx / NH;
        int w = idx - j * NH;
        float2 p = *(const float2*)(xi + (2 * j + 1) * H + 2 * w);
        BufB[j * LD + w] = p.x;
        BufA[j * LD + w] = p.y;
        s_local += ((j + w) & 1) ? -p.y : p.y;
    }
    #pragma unroll
    for (int o = 16; o; o >>= 1) s_local += __shfl_xor_sync(0xffffffffu, s_local, o);
    if ((tid & 31) == 0) sred[tid >> 5] = s_local;
    __syncthreads();

    const int row0 = ty;            // rows handled: ty + 16*i
    const int col0 = tx;            // cols handled: tx + 16*c

    // ---- GEMM1a: T_oo = R * x_oo; overwrite BufA with G2 = T_oo + 0.5*x_eo
    {
        u64 acc2[7][3]; float acc1[7];
        #pragma unroll
        for (int i = 0; i < 7; ++i) {
            acc1[i] = 0.f;
            #pragma unroll
            for (int p = 0; p < 3; ++p) acc2[i][p] = 0ull;
        }

        for (int j = 0; j < NH; ++j) {
            float a_[7];
            #pragma unroll
            for (int c = 0; c < 7; ++c) a_[c] = BufA[j * LD + col0 + 16 * c];
            u64 ap[3];
            #pragma unroll
            for (int p = 0; p < 3; ++p) ap[p] = pack2(a_[2 * p], a_[2 * p + 1]);
            #pragma unroll
            for (int i = 0; i < 7; ++i) {
                float r = cor2[row0 + 16 * i - j + NH];
                u64 rp = pack2(r, r);
                #pragma unroll
                for (int p = 0; p < 3; ++p) fma2(acc2[i][p], rp, ap[p]);
                acc1[i] = fmaf(r, a_[6], acc1[i]);
            }
        }
        __syncthreads();
        #pragma unroll
        for (int i = 0; i < 7; ++i) {
            int n1 = row0 + 16 * i;
            #pragma unroll
            for (int p = 0; p < 3; ++p) {
                float2 v = unpack2(acc2[i][p]);
                int ja = col0 + 32 * p, jb = ja + 16;
                BufA[n1 * LD + ja] = v.x + 0.5f * xi[(2 * n1) * H + 2 * ja + 1];
                BufA[n1 * LD + jb] = v.y + 0.5f * xi[(2 * n1) * H + 2 * jb + 1];
            }
            int jc = col0 + 96;
            BufA[n1 * LD + jc] = acc1[i] + 0.5f * xi[(2 * n1) * H + 2 * jc + 1];
        }
        __syncthreads();
    }

    // ---- GEMM1b: T_oe = R * x_oe; overwrite BufB with Epre = 0.5*T_oe + 0.25*x_ee
    {
        u64 acc2[7][3]; float acc1[7];
        #pragma unroll
        for (int i = 0; i < 7; ++i) {
            acc1[i] = 0.f;
            #pragma unroll
            for (int p = 0; p < 3; ++p) acc2[i][p] = 0ull;
        }

        for (int j = 0; j < NH; ++j) {
            float b_[7];
            #pragma unroll
            for (int c = 0; c < 7; ++c) b_[c] = BufB[j * LD + col0 + 16 * c];
            u64 bp[3];
            #pragma unroll
            for (int p = 0; p < 3; ++p) bp[p] = pack2(b_[2 * p], b_[2 * p + 1]);
            #pragma unroll
            for (int i = 0; i < 7; ++i) {
                float r = cor2[row0 + 16 * i - j + NH];
                u64 rp = pack2(r, r);
                #pragma unroll
                for (int p = 0; p < 3; ++p) fma2(acc2[i][p], rp, bp[p]);
                acc1[i] = fmaf(r, b_[6], acc1[i]);
            }
        }
        __syncthreads();
        #pragma unroll
        for (int i = 0; i < 7; ++i) {
            int n1 = row0 + 16 * i;
            #pragma unroll
            for (int p = 0; p < 3; ++p) {
                float2 v = unpack2(acc2[i][p]);
                int na = col0 + 32 * p, nb = na + 16;
                BufB[n1 * LD + na] = 0.5f * v.x + 0.25f * xi[(2 * n1) * H + 2 * na];
                BufB[n1 * LD + nb] = 0.5f * v.y + 0.25f * xi[(2 * n1) * H + 2 * nb];
            }
            int nc = col0 + 96;
            BufB[n1 * LD + nc] = 0.5f * acc1[i] + 0.25f * xi[(2 * n1) * H + 2 * nc];
        }
        __syncthreads();
    }

    float stot = 0.f;
    #pragma unroll
    for (int wi = 0; wi < 8; ++wi) stot += sred[wi];
    const float scorr = stot * (1.0f / 50176.0f);   // s / 224^2

    // ---- GEMM2: out = G2 * R^T + Epre -/+ scorr
    // out[n1][n2] = sum_j2 G2[n1][j2] * cor2[n2 - j2 + NH]
    {
        u64 acc2[7][3]; float acc1[7];
        #pragma unroll
        for (int i = 0; i < 7; ++i) {
            acc1[i] = 0.f;
            #pragma unroll
            for (int p = 0; p < 3; ++p) acc2[i][p] = 0ull;
        }

        for (int j2 = 0; j2 < NH; ++j2) {
            float r_[7];
            #pragma unroll
            for (int c = 0; c < 7; ++c) r_[c] = cor2[col0 + 16 * c - j2 + NH];
            u64 rp[3];
            #pragma unroll
            for (int p = 0; p < 3; ++p) rp[p] = pack2(r_[2 * p], r_[2 * p + 1]);
            #pragma unroll
            for (int i = 0; i < 7; ++i) {
                float g = BufA[(row0 + 16 * i) * LD + j2];
                u64 gp = pack2(g, g);
                #pragma unroll
                for (int p = 0; p < 3; ++p) fma2(acc2[i][p], gp, rp[p]);
                acc1[i] = fmaf(g, r_[6], acc1[i]);
            }
        }

        #pragma unroll
        for (int i = 0; i < 7; ++i) {
            int n1 = row0 + 16 * i;
            #pragma unroll
            for (int p = 0; p < 3; ++p) {
                float2 v = unpack2(acc2[i][p]);
                int na = col0 + 32 * p, nb = na + 16;
                float ra = v.x + BufB[n1 * LD + na];
                float rb = v.y + BufB[n1 * LD + nb];
                ra += ((n1 + na) & 1) ? scorr : -scorr;
                rb += ((n1 + nb) & 1) ? scorr : -scorr;
                oi[n1 * NH + na] = ra;
                oi[n1 * NH + nb] = rb;
            }
            int nc = col0 + 96;
            float rc = acc1[i] + BufB[n1 * LD + nc];
            rc += ((n1 + nc) & 1) ? scorr : -scorr;
            oi[n1 * NH + nc] = rc;
        }
    }
}

extern "C" void kernel_launch(void* const* d_in, const int* in_sizes, int n_in,
                              void* d_out, int out_size) {
    (void)in_sizes; (void)n_in; (void)out_size;
    const float* x = (const float*)d_in[0];
    float* out = (float*)d_out;

    const int smem_bytes = (2 * NH * LD + 2 * NH + 8) * (int)sizeof(float);
    cudaFuncSetAttribute(flc_main_kernel,
                         cudaFuncAttributeMaxDynamicSharedMemorySize, smem_bytes);

    flc_main_kernel<<<NIMG, 256, smem_bytes>>>(x, out);
}